// round 6
// baseline (speedup 1.0000x reference)
#include <cuda_runtime.h>
#include <cstdint>

// SNN Leaky forward:  mem = 0.5*mem + x_t - spk;  spk = (mem > 1) ? 1 : 0
// x: [128, 64*4096] f32 -> spk same shape. Pure HBM streaming.
//
// R6 = R5 (38.4us kernel, DRAM 69.5%, eff 7.0TB/s) + burst separation:
//  - phase-split inner loop: 8 batched LDG.128 -> 8 reg-only compute
//    steps -> 8 batched STG.128. Longer read/write bursts at the memory
//    controller, fewer bus turnarounds.
//  - PF_DIST 16 -> 24 (24MB L2 footprint), prefetch issued before loads.

#define T_STEPS 128
#define BN4 65536                 // (64*4096)/4 float4 columns per timestep
#define BLOCK 64
#define PF_DIST 24                // timesteps of prefetch lead
#define PF_BYTES (BLOCK * 16)     // 1KB slab per CTA per timestep

__device__ __forceinline__ void l2_prefetch(const void* p, uint32_t bytes) {
    asm volatile("cp.async.bulk.prefetch.L2.global [%0], %1;"
                 :: "l"(p), "r"(bytes) : "memory");
}

__global__ __launch_bounds__(BLOCK) void snn_leaky_kernel(
    const float4* __restrict__ x4, float4* __restrict__ o4)
{
    const int idx = blockIdx.x * BLOCK + threadIdx.x;   // 0..BN4-1
    const float4* xp = x4 + idx;
    float4* op = o4 + idx;

    // CTA's contiguous 1KB slab base for prefetching
    const float4* pf_base = x4 + blockIdx.x * BLOCK;

    // prologue: prefetch timesteps 0..PF_DIST-1
    if (threadIdx.x == 0) {
#pragma unroll
        for (int t = 0; t < PF_DIST; t++)
            l2_prefetch(pf_base + (size_t)t * BN4, PF_BYTES);
    }

    float4 mem = make_float4(0.f, 0.f, 0.f, 0.f);
    float4 spk = make_float4(0.f, 0.f, 0.f, 0.f);

    for (int t = 0; t < T_STEPS; t += 8) {
        // keep the async prefetch engine PF_DIST steps ahead
        if (threadIdx.x == 0 && t + PF_DIST < T_STEPS) {
#pragma unroll
            for (int u = 0; u < 8; u++)
                l2_prefetch(pf_base + (size_t)(t + PF_DIST + u) * BN4, PF_BYTES);
        }

        // phase 1: 8 batched loads (read burst, mostly L2 hits)
        float4 a[8];
#pragma unroll
        for (int u = 0; u < 8; u++)
            a[u] = __ldcs(xp + (size_t)(t + u) * BN4);

        // phase 2: 8 recurrence steps, registers only
        float4 s[8];
#pragma unroll
        for (int u = 0; u < 8; u++) {
            mem.x = 0.5f * mem.x + a[u].x - spk.x;
            mem.y = 0.5f * mem.y + a[u].y - spk.y;
            mem.z = 0.5f * mem.z + a[u].z - spk.z;
            mem.w = 0.5f * mem.w + a[u].w - spk.w;

            spk.x = (mem.x > 1.0f) ? 1.0f : 0.0f;
            spk.y = (mem.y > 1.0f) ? 1.0f : 0.0f;
            spk.z = (mem.z > 1.0f) ? 1.0f : 0.0f;
            spk.w = (mem.w > 1.0f) ? 1.0f : 0.0f;

            s[u] = spk;
        }

        // phase 3: 8 batched stores (write burst)
#pragma unroll
        for (int u = 0; u < 8; u++)
            __stcs(op + (size_t)(t + u) * BN4, s[u]);
    }
}

extern "C" void kernel_launch(void* const* d_in, const int* in_sizes, int n_in,
                              void* d_out, int out_size)
{
    const float4* x4 = (const float4*)d_in[0];
    float4* o4 = (float4*)d_out;
    snn_leaky_kernel<<<BN4 / BLOCK, BLOCK>>>(x4, o4);
}